// round 2
// baseline (speedup 1.0000x reference)
#include <cuda_runtime.h>
#include <cstdint>

// SimpleGNNBlock: out[b,k] = sum_p relu( relu(feats[b,p,:] @ W1 + b1) @ W2 + b2 )
// feats = [dx, dy, 1/sqrt(dx^2+dy^2+1e-6), m_p]
// B=32768, P=128, H=64.
//
// Strategy: fused kernel. Layer-2 GEMM on tensor cores via mma.sync tf32
// (fp32 accumulate), layer-1 scalar with register-resident W1 constants.

#define BATCHES 32768
#define PP 128
#define HH 64

#define GRID 4096
#define BPC (BATCHES / GRID)   // batches per CTA = 8

#define HS_STRIDE 68           // 68 % 32 == 4 -> conflict-free A-frag reads

__device__ __forceinline__ uint32_t f2tf32(float x) {
    uint32_t u;
    asm("cvt.rna.tf32.f32 %0, %1;" : "=r"(u) : "f"(x));
    return u;
}

__global__ __launch_bounds__(128, 6)
void gnn_kernel(const float* __restrict__ planet_xy,   // (B,P,2)
                const float* __restrict__ planet_m,    // (P)
                const float* __restrict__ ast_xy,      // (B,2)
                const float* __restrict__ W1,          // (4,H) row-major
                const float* __restrict__ b1,          // (H)
                const float* __restrict__ W2,          // (H,H) row-major [j][k]
                const float* __restrict__ b2,          // (H)
                float* __restrict__ out)               // (B,H)
{
    __shared__ float  h_s[64 * HS_STRIDE];   // half-batch of h rows (tf32 bits)
    __shared__ float2 Bf[8 * 8 * 32];        // W2 fragments: [kt][n][lane] = {B[k][n], B[k+4][n]}
    __shared__ float4 feats_s[PP];           // per-p features for current batch
    __shared__ float  sacc[HH];
    __shared__ float  b2s[HH];

    const int tid  = threadIdx.x;
    const int lane = tid & 31;
    const int w    = tid >> 5;     // warp 0..3
    const int g    = lane >> 2;    // groupID 0..7
    const int tig  = lane & 3;     // thread-in-group 0..3

    // ---- one-time per CTA: pack W2 into MMA B-fragment layout (tf32) ----
    for (int idx = tid; idx < 8 * 8 * 32; idx += 128) {
        int kt = idx >> 8;            // 0..7
        int n  = (idx >> 5) & 7;      // 0..7
        int l  = idx & 31;
        int tt = l & 3, gg = l >> 2;
        int col = n * 8 + gg;         // output channel
        // B[k][n] = W2[k][n] (k = hidden dim j)
        float v0 = W2[(kt * 8 + tt) * HH + col];
        float v1 = W2[(kt * 8 + tt + 4) * HH + col];
        Bf[idx] = make_float2(__uint_as_float(f2tf32(v0)),
                              __uint_as_float(f2tf32(v1)));
    }
    if (tid < HH) b2s[tid] = b2[tid];

    // layer-1 per-thread constants: thread owns hidden channel kk = tid%64
    const int   kk  = tid & 63;
    const float w0  = W1[0 * HH + kk];
    const float w1  = W1[1 * HH + kk];
    const float w2  = W1[2 * HH + kk];
    const float w3  = W1[3 * HH + kk];
    const float b1v = b1[kk];
    const float mval = planet_m[tid];   // tid == p for feats stage (tid < 128)

    __syncthreads();

    for (int it = 0; it < BPC; ++it) {
        const int b = blockIdx.x + it * GRID;

        // ---- feats: one thread per p ----
        if (tid < HH) sacc[tid] = 0.0f;
        float2 pxy = reinterpret_cast<const float2*>(planet_xy)[b * PP + tid];
        float ax = ast_xy[2 * b], ay = ast_xy[2 * b + 1];
        float dx = pxy.x - ax;
        float dy = pxy.y - ay;
        float inv = rsqrtf(fmaf(dx, dx, fmaf(dy, dy, 1e-6f)));
        feats_s[tid] = make_float4(dx, dy, inv, mval);
        __syncthreads();

        // process p in two halves of 64 rows to keep h_s at 17 KB
        #pragma unroll
        for (int half = 0; half < 2; ++half) {
            // ---- layer 1: h[row][kk] for local rows 0..63 ----
            {
                const int rbase = (tid >> 6) * 32;   // thread group 0/1 -> rows 0..31 / 32..63
                #pragma unroll 8
                for (int i = 0; i < 32; ++i) {
                    int row = rbase + i;
                    float4 f = feats_s[half * 64 + row];   // warp-uniform -> broadcast LDS.128
                    float hv = fmaf(f.x, w0, b1v);
                    hv = fmaf(f.y, w1, hv);
                    hv = fmaf(f.z, w2, hv);
                    hv = fmaf(f.w, w3, hv);
                    hv = fmaxf(hv, 0.0f);
                    h_s[row * HS_STRIDE + kk] = __uint_as_float(f2tf32(hv));
                }
            }
            __syncthreads();

            // ---- layer 2: each warp computes 16 rows x 64 cols via 64 MMAs ----
            float c[8][4];
            #pragma unroll
            for (int n = 0; n < 8; ++n) {
                c[n][0] = 0.f; c[n][1] = 0.f; c[n][2] = 0.f; c[n][3] = 0.f;
            }
            const int r0 = w * 16 + g;   // local row for a0/a2 (a1/a3 use +8)
            #pragma unroll
            for (int kt = 0; kt < 8; ++kt) {
                uint32_t a0 = __float_as_uint(h_s[r0       * HS_STRIDE + kt * 8 + tig]);
                uint32_t a1 = __float_as_uint(h_s[(r0 + 8) * HS_STRIDE + kt * 8 + tig]);
                uint32_t a2 = __float_as_uint(h_s[r0       * HS_STRIDE + kt * 8 + tig + 4]);
                uint32_t a3 = __float_as_uint(h_s[(r0 + 8) * HS_STRIDE + kt * 8 + tig + 4]);
                #pragma unroll
                for (int n = 0; n < 8; ++n) {
                    float2 bb = Bf[(kt * 8 + n) * 32 + lane];
                    uint32_t bb0 = __float_as_uint(bb.x);
                    uint32_t bb1 = __float_as_uint(bb.y);
                    asm volatile(
                        "mma.sync.aligned.m16n8k8.row.col.f32.tf32.tf32.f32 "
                        "{%0,%1,%2,%3}, {%4,%5,%6,%7}, {%8,%9}, {%0,%1,%2,%3};"
                        : "+f"(c[n][0]), "+f"(c[n][1]), "+f"(c[n][2]), "+f"(c[n][3])
                        : "r"(a0), "r"(a1), "r"(a2), "r"(a3), "r"(bb0), "r"(bb1));
                }
            }

            // ---- epilogue: relu(+b2), reduce over the warp's 16 rows ----
            #pragma unroll
            for (int n = 0; n < 8; ++n) {
                int col0 = n * 8 + 2 * tig;
                float bb0 = b2s[col0];
                float bb1 = b2s[col0 + 1];
                float v0 = fmaxf(c[n][0] + bb0, 0.f) + fmaxf(c[n][2] + bb0, 0.f);
                float v1 = fmaxf(c[n][1] + bb1, 0.f) + fmaxf(c[n][3] + bb1, 0.f);
                v0 += __shfl_xor_sync(0xffffffffu, v0, 4);
                v1 += __shfl_xor_sync(0xffffffffu, v1, 4);
                v0 += __shfl_xor_sync(0xffffffffu, v0, 8);
                v1 += __shfl_xor_sync(0xffffffffu, v1, 8);
                v0 += __shfl_xor_sync(0xffffffffu, v0, 16);
                v1 += __shfl_xor_sync(0xffffffffu, v1, 16);
                if (g == 0) {
                    atomicAdd(&sacc[col0],     v0);
                    atomicAdd(&sacc[col0 + 1], v1);
                }
            }
            __syncthreads();   // h_s reads + sacc atomics done before reuse
        }

        // ---- store ----
        if (tid < HH) out[b * HH + tid] = sacc[tid];
        __syncthreads();   // protect sacc/feats_s before next batch
    }
}

extern "C" void kernel_launch(void* const* d_in, const int* in_sizes, int n_in,
                              void* d_out, int out_size) {
    (void)in_sizes; (void)n_in; (void)out_size;
    const float* planet_xy = (const float*)d_in[0];
    const float* planet_m  = (const float*)d_in[1];
    const float* ast_xy    = (const float*)d_in[2];
    const float* W1        = (const float*)d_in[3];
    const float* b1        = (const float*)d_in[4];
    const float* W2        = (const float*)d_in[5];
    const float* b2        = (const float*)d_in[6];
    float* out             = (float*)d_out;

    gnn_kernel<<<GRID, 128>>>(planet_xy, planet_m, ast_xy, W1, b1, W2, b2, out);
}